// round 14
// baseline (speedup 1.0000x reference)
#include <cuda_runtime.h>

// out[w*2048+h] = -dot(weight3x3, x[3w:3w+3, 3h:3h+3]) / 0.924458
// x: 6144x6144 fp32 -> out: 2048x2048 fp32. Pure HBM stream (168 MB).
// R8 winning shape (one-shot grid 4096x256, 4 outputs/thread, 9 coalesced
// float4 __ldcs loads, folded scale) + single change: __stwt write-through
// store, streaming writes into DRAM instead of bursty L2 dirty-evictions
// that collide with the read stream.

#define XW 6144
#define NH 2048
#define GROUPS_PER_ROW 512  // NH / 4

__global__ __launch_bounds__(256) void conv3x3_stride3_kernel(
    const float* __restrict__ x,
    const float* __restrict__ wgt,
    float* __restrict__ out)
{
    int idx = blockIdx.x * blockDim.x + threadIdx.x;   // 0 .. 2048*512-1
    int w = idx >> 9;                      // output row
    int g = idx & (GROUPS_PER_ROW - 1);    // horizontal group of 4 outputs

    const float scale = (float)(-1.0 / 0.924458);
    float k0 = wgt[0] * scale, k1 = wgt[1] * scale, k2 = wgt[2] * scale;
    float k3 = wgt[3] * scale, k4 = wgt[4] * scale, k5 = wgt[5] * scale;
    float k6 = wgt[6] * scale, k7 = wgt[7] * scale, k8 = wgt[8] * scale;

    // rows 3w..3w+2, starting column 12*g (48B-aligned)
    const float* base = x + (size_t)(3 * w) * XW + 12 * g;

    float4 a0 = __ldcs((const float4*)(base));
    float4 a1 = __ldcs((const float4*)(base + 4));
    float4 a2 = __ldcs((const float4*)(base + 8));
    float4 b0 = __ldcs((const float4*)(base + XW));
    float4 b1 = __ldcs((const float4*)(base + XW + 4));
    float4 b2 = __ldcs((const float4*)(base + XW + 8));
    float4 c0 = __ldcs((const float4*)(base + 2 * XW));
    float4 c1 = __ldcs((const float4*)(base + 2 * XW + 4));
    float4 c2 = __ldcs((const float4*)(base + 2 * XW + 8));

    float r0[12] = {a0.x, a0.y, a0.z, a0.w, a1.x, a1.y, a1.z, a1.w, a2.x, a2.y, a2.z, a2.w};
    float r1[12] = {b0.x, b0.y, b0.z, b0.w, b1.x, b1.y, b1.z, b1.w, b2.x, b2.y, b2.z, b2.w};
    float r2[12] = {c0.x, c0.y, c0.z, c0.w, c1.x, c1.y, c1.z, c1.w, c2.x, c2.y, c2.z, c2.w};

    float4 res;
    float* rp = (float*)&res;
#pragma unroll
    for (int j = 0; j < 4; j++) {
        rp[j] = k0 * r0[3*j] + k1 * r0[3*j+1] + k2 * r0[3*j+2]
              + k3 * r1[3*j] + k4 * r1[3*j+1] + k5 * r1[3*j+2]
              + k6 * r2[3*j] + k7 * r2[3*j+1] + k8 * r2[3*j+2];
    }

    // output float4 index == idx (w*512 + g); write-through streaming store
    __stwt((float4*)out + idx, res);
}

extern "C" void kernel_launch(void* const* d_in, const int* in_sizes, int n_in,
                              void* d_out, int out_size)
{
    const float* x   = (const float*)d_in[0];
    const float* wgt = (const float*)d_in[1];
    float* out = (float*)d_out;

    int total_threads = NH * GROUPS_PER_ROW;   // 1,048,576
    int block = 256;
    int grid = total_threads / block;          // 4096
    conv3x3_stride3_kernel<<<grid, block>>>(x, wgt, out);
}

// round 15
// speedup vs baseline: 1.0011x; 1.0011x over previous
#include <cuda_runtime.h>

// out[w*2048+h] = -dot(weight3x3, x[3w:3w+3, 3h:3h+3]) / 0.924458
// x: 6144x6144 fp32 -> out: 2048x2048 fp32. Pure HBM stream (168 MB).
// R8 winning shape (one-shot grid 4096x256, 4 outputs/thread, 9 coalesced
// float4 __ldcs loads, folded scale) + single change: __stwt write-through
// store, streaming writes into DRAM instead of bursty L2 dirty-evictions
// that collide with the read stream.

#define XW 6144
#define NH 2048
#define GROUPS_PER_ROW 512  // NH / 4

__global__ __launch_bounds__(256) void conv3x3_stride3_kernel(
    const float* __restrict__ x,
    const float* __restrict__ wgt,
    float* __restrict__ out)
{
    int idx = blockIdx.x * blockDim.x + threadIdx.x;   // 0 .. 2048*512-1
    int w = idx >> 9;                      // output row
    int g = idx & (GROUPS_PER_ROW - 1);    // horizontal group of 4 outputs

    const float scale = (float)(-1.0 / 0.924458);
    float k0 = wgt[0] * scale, k1 = wgt[1] * scale, k2 = wgt[2] * scale;
    float k3 = wgt[3] * scale, k4 = wgt[4] * scale, k5 = wgt[5] * scale;
    float k6 = wgt[6] * scale, k7 = wgt[7] * scale, k8 = wgt[8] * scale;

    // rows 3w..3w+2, starting column 12*g (48B-aligned)
    const float* base = x + (size_t)(3 * w) * XW + 12 * g;

    float4 a0 = __ldcs((const float4*)(base));
    float4 a1 = __ldcs((const float4*)(base + 4));
    float4 a2 = __ldcs((const float4*)(base + 8));
    float4 b0 = __ldcs((const float4*)(base + XW));
    float4 b1 = __ldcs((const float4*)(base + XW + 4));
    float4 b2 = __ldcs((const float4*)(base + XW + 8));
    float4 c0 = __ldcs((const float4*)(base + 2 * XW));
    float4 c1 = __ldcs((const float4*)(base + 2 * XW + 4));
    float4 c2 = __ldcs((const float4*)(base + 2 * XW + 8));

    float r0[12] = {a0.x, a0.y, a0.z, a0.w, a1.x, a1.y, a1.z, a1.w, a2.x, a2.y, a2.z, a2.w};
    float r1[12] = {b0.x, b0.y, b0.z, b0.w, b1.x, b1.y, b1.z, b1.w, b2.x, b2.y, b2.z, b2.w};
    float r2[12] = {c0.x, c0.y, c0.z, c0.w, c1.x, c1.y, c1.z, c1.w, c2.x, c2.y, c2.z, c2.w};

    float4 res;
    float* rp = (float*)&res;
#pragma unroll
    for (int j = 0; j < 4; j++) {
        rp[j] = k0 * r0[3*j] + k1 * r0[3*j+1] + k2 * r0[3*j+2]
              + k3 * r1[3*j] + k4 * r1[3*j+1] + k5 * r1[3*j+2]
              + k6 * r2[3*j] + k7 * r2[3*j+1] + k8 * r2[3*j+2];
    }

    // output float4 index == idx (w*512 + g); write-through streaming store
    __stwt((float4*)out + idx, res);
}

extern "C" void kernel_launch(void* const* d_in, const int* in_sizes, int n_in,
                              void* d_out, int out_size)
{
    const float* x   = (const float*)d_in[0];
    const float* wgt = (const float*)d_in[1];
    float* out = (float*)d_out;

    int total_threads = NH * GROUPS_PER_ROW;   // 1,048,576
    int block = 256;
    int grid = total_threads / block;          // 4096
    conv3x3_stride3_kernel<<<grid, block>>>(x, wgt, out);
}

// round 16
// speedup vs baseline: 1.0349x; 1.0337x over previous
#include <cuda_runtime.h>

// out[w*2048+h] = -dot(weight3x3, x[3w:3w+3, 3h:3h+3]) / 0.924458
// x: 6144x6144 fp32 -> out: 2048x2048 fp32. Pure HBM stream (168 MB).
// R8 winning shape (one-shot grid 4096x256, 4 outputs/thread, 9 coalesced
// float4 __ldcs loads, folded scale) + single change: __stwt write-through
// store, streaming writes into DRAM instead of bursty L2 dirty-evictions
// that collide with the read stream.

#define XW 6144
#define NH 2048
#define GROUPS_PER_ROW 512  // NH / 4

__global__ __launch_bounds__(256) void conv3x3_stride3_kernel(
    const float* __restrict__ x,
    const float* __restrict__ wgt,
    float* __restrict__ out)
{
    int idx = blockIdx.x * blockDim.x + threadIdx.x;   // 0 .. 2048*512-1
    int w = idx >> 9;                      // output row
    int g = idx & (GROUPS_PER_ROW - 1);    // horizontal group of 4 outputs

    const float scale = (float)(-1.0 / 0.924458);
    float k0 = wgt[0] * scale, k1 = wgt[1] * scale, k2 = wgt[2] * scale;
    float k3 = wgt[3] * scale, k4 = wgt[4] * scale, k5 = wgt[5] * scale;
    float k6 = wgt[6] * scale, k7 = wgt[7] * scale, k8 = wgt[8] * scale;

    // rows 3w..3w+2, starting column 12*g (48B-aligned)
    const float* base = x + (size_t)(3 * w) * XW + 12 * g;

    float4 a0 = __ldcs((const float4*)(base));
    float4 a1 = __ldcs((const float4*)(base + 4));
    float4 a2 = __ldcs((const float4*)(base + 8));
    float4 b0 = __ldcs((const float4*)(base + XW));
    float4 b1 = __ldcs((const float4*)(base + XW + 4));
    float4 b2 = __ldcs((const float4*)(base + XW + 8));
    float4 c0 = __ldcs((const float4*)(base + 2 * XW));
    float4 c1 = __ldcs((const float4*)(base + 2 * XW + 4));
    float4 c2 = __ldcs((const float4*)(base + 2 * XW + 8));

    float r0[12] = {a0.x, a0.y, a0.z, a0.w, a1.x, a1.y, a1.z, a1.w, a2.x, a2.y, a2.z, a2.w};
    float r1[12] = {b0.x, b0.y, b0.z, b0.w, b1.x, b1.y, b1.z, b1.w, b2.x, b2.y, b2.z, b2.w};
    float r2[12] = {c0.x, c0.y, c0.z, c0.w, c1.x, c1.y, c1.z, c1.w, c2.x, c2.y, c2.z, c2.w};

    float4 res;
    float* rp = (float*)&res;
#pragma unroll
    for (int j = 0; j < 4; j++) {
        rp[j] = k0 * r0[3*j] + k1 * r0[3*j+1] + k2 * r0[3*j+2]
              + k3 * r1[3*j] + k4 * r1[3*j+1] + k5 * r1[3*j+2]
              + k6 * r2[3*j] + k7 * r2[3*j+1] + k8 * r2[3*j+2];
    }

    // output float4 index == idx (w*512 + g); write-through streaming store
    __stwt((float4*)out + idx, res);
}

extern "C" void kernel_launch(void* const* d_in, const int* in_sizes, int n_in,
                              void* d_out, int out_size)
{
    const float* x   = (const float*)d_in[0];
    const float* wgt = (const float*)d_in[1];
    float* out = (float*)d_out;

    int total_threads = NH * GROUPS_PER_ROW;   // 1,048,576
    int block = 256;
    int grid = total_threads / block;          // 4096
    conv3x3_stride3_kernel<<<grid, block>>>(x, wgt, out);
}